// round 6
// baseline (speedup 1.0000x reference)
#include <cuda_runtime.h>
#include <cuda_bf16.h>
#include <cstdint>
#include <math.h>

#define BATCH 4
#define CHN   512
#define HW    4096
#define EPSF  1e-5f

using bf16 = __nv_bfloat16;

// ---------------- scratch (device globals; no allocations allowed) ----------
__device__ bf16 g_CN_h[BATCH * CHN * HW], g_CN_l[BATCH * CHN * HW];  // norm(content)^T [b][n][c]
__device__ bf16 g_SN_h[BATCH * CHN * HW], g_SN_l[BATCH * CHN * HW];  // norm(style)^T
__device__ bf16 g_St_h[BATCH * CHN * HW], g_St_l[BATCH * CHN * HW];  // style^T
__device__ bf16 g_F_h[BATCH * CHN * HW],  g_F_l[BATCH * CHN * HW];   // F_t [b][n][c]
__device__ bf16 g_G_h[BATCH * CHN * HW],  g_G_l[BATCH * CHN * HW];   // G_t [b][n][c]
__device__ bf16 g_H_h[BATCH * CHN * HW],  g_H_l[BATCH * CHN * HW];   // H [b][c][m]
__device__ bf16 g_O_h[BATCH * CHN * HW],  g_O_l[BATCH * CHN * HW];   // O_t [b][n][c]
__device__ bf16 g_P_h[(size_t)BATCH * HW * HW], g_P_l[(size_t)BATCH * HW * HW]; // softmax(S)
__device__ float g_S[(size_t)BATCH * HW * HW];                        // S fp32
__device__ bf16 g_Wf_h[CHN * CHN], g_Wf_l[CHN * CHN];
__device__ bf16 g_Wg_h[CHN * CHN], g_Wg_l[CHN * CHN];
__device__ bf16 g_Wh_h[CHN * CHN], g_Wh_l[CHN * CHN];
__device__ bf16 g_Wo_h[CHN * CHN], g_Wo_l[CHN * CHN];
__device__ float g_mean[2 * BATCH * CHN];
__device__ float g_rstd[2 * BATCH * CHN];

// ============================ helpers =======================================
__device__ __forceinline__ uint32_t smem_to_u32(const void* p) {
    uint32_t a;
    asm("{ .reg .u64 t; cvta.to.shared.u64 t, %1; cvt.u32.u64 %0, t; }"
        : "=r"(a) : "l"(p));
    return a;
}
__device__ __forceinline__ void cp_async16(uint32_t saddr, const void* g) {
    asm volatile("cp.async.ca.shared.global [%0], [%1], 16;"
                 :: "r"(saddr), "l"(g) : "memory");
}
#define CP_COMMIT() asm volatile("cp.async.commit_group;" ::: "memory")
#define CP_WAIT2()  asm volatile("cp.async.wait_group 2;" ::: "memory")

__device__ __forceinline__ uint32_t pack_bf16x2(float lo, float hi) {
    uint32_t r;
    asm("cvt.rn.bf16x2.f32 %0, %1, %2;" : "=r"(r) : "f"(hi), "f"(lo));
    return r;
}
// split (x,y) into bf16 hi/lo packs and store to planes at byte-identical offset
__device__ __forceinline__ void split2_store(float x, float y,
                                             bf16* __restrict__ Ch,
                                             bf16* __restrict__ Cl, size_t off) {
    uint32_t h = pack_bf16x2(x, y);
    float hx = __uint_as_float(h << 16);
    float hy = __uint_as_float(h & 0xffff0000u);
    uint32_t l = pack_bf16x2(x - hx, y - hy);
    *(uint32_t*)(Ch + off) = h;
    *(uint32_t*)(Cl + off) = l;
}

__device__ __forceinline__ void mma_bf16(float* d, const uint32_t* a, const uint32_t* b) {
    asm volatile(
        "mma.sync.aligned.m16n8k16.row.col.f32.bf16.bf16.f32 "
        "{%0,%1,%2,%3}, {%4,%5,%6,%7}, {%8,%9}, {%0,%1,%2,%3};"
        : "+f"(d[0]), "+f"(d[1]), "+f"(d[2]), "+f"(d[3])
        : "r"(a[0]), "r"(a[1]), "r"(a[2]), "r"(a[3]), "r"(b[0]), "r"(b[1]));
}
__device__ __forceinline__ void ldmat4(uint32_t* d, uint32_t a) {
    asm volatile("ldmatrix.sync.aligned.m8n8.x4.shared.b16 {%0,%1,%2,%3}, [%4];"
        : "=r"(d[0]), "=r"(d[1]), "=r"(d[2]), "=r"(d[3]) : "r"(a));
}

// =================== pre-split bf16 3-term GEMM (NT) ========================
// D[m,n] = sum_k A[m,k]*B[n,k], A/B given as bf16 hi/lo planes, row-major.
// 128x128 CTA tile, 8 warps (2x4), warp tile 64x32, BK=32, 4-stage cp.async.
// BIASMODE: 0 none, 1 bias[m], 2 bias[n].  OUTMODE: 0 fp32, 1 split bf16,
// 2 fp32 + residual.
#define GK_ROWU   20                              // u32 per smem row (16+4 pad)
#define GK_MATU   (128 * GK_ROWU)                 // 2560 u32 per plane
#define GK_MATB   (GK_MATU * 4)
#define GK_STAGEU (4 * GK_MATU)                   // Ahi,Alo,Bhi,Blo
#define GK_SMEMB  (4 * GK_STAGEU * 4)             // 163840 bytes

template<int BIASMODE, int OUTMODE>
__global__ void __launch_bounds__(256, 1)
gemm2(const bf16* __restrict__ Ah, const bf16* __restrict__ Al,
      const bf16* __restrict__ Bh, const bf16* __restrict__ Bl,
      const float* __restrict__ bias, const float* __restrict__ residg,
      float* __restrict__ Cf, bf16* __restrict__ Ch, bf16* __restrict__ Cl,
      int K, int ldA, int ldB, int ldC,
      size_t sA, size_t sB, size_t sC)
{
    extern __shared__ uint32_t smem_u32[];
    const uint32_t sb = smem_to_u32(smem_u32);

    const int t    = threadIdx.x;
    const int lane = t & 31;
    const int wid  = t >> 5;
    const int wm   = wid >> 2;
    const int wn   = wid & 3;
    const int r0   = lane >> 2;
    const int c0   = lane & 3;

    const int b  = blockIdx.z;
    const int m0 = blockIdx.y * 128, n0 = blockIdx.x * 128;
    const bf16* pAh = Ah + (size_t)b * sA + (size_t)m0 * ldA;
    const bf16* pAl = Al + (size_t)b * sA + (size_t)m0 * ldA;
    const bf16* pBh = Bh + (size_t)b * sB + (size_t)n0 * ldB;
    const bf16* pBl = Bl + (size_t)b * sB + (size_t)n0 * ldB;

    const int NC = K >> 5;
    const int lrow = t >> 2, lch = t & 3;          // loader: rows t>>2, +64

    auto issue = [&](int c) {
        if (c < NC) {
            const int k0 = c << 5;
            const uint32_t sbase = sb + ((c & 3) * GK_STAGEU) * 4;
            #pragma unroll
            for (int i = 0; i < 2; i++) {
                int row = lrow + i * 64;
                uint32_t so = sbase + (uint32_t)(row * GK_ROWU + lch * 4) * 4;
                size_t go = (size_t)row;
                cp_async16(so,               pAh + go * ldA + k0 + lch * 8);
                cp_async16(so + GK_MATB,     pAl + go * ldA + k0 + lch * 8);
                cp_async16(so + 2 * GK_MATB, pBh + go * ldB + k0 + lch * 8);
                cp_async16(so + 3 * GK_MATB, pBl + go * ldB + k0 + lch * 8);
            }
        }
        CP_COMMIT();
    };

    const uint32_t laneRow = lane & 15;
    const uint32_t laneC4  = (lane >> 4) * 4;

    float acc[4][4][4] = {};

    issue(0); issue(1); issue(2);

    for (int c = 0; c < NC; c++) {
        CP_WAIT2();
        __syncthreads();
        const uint32_t sbase = sb + ((c & 3) * GK_STAGEU) * 4;

        #pragma unroll
        for (int kk = 0; kk < 2; kk++) {
            uint32_t ah[4][4], al[4][4], bh[4][2], bl[4][2];
            const uint32_t coff = (kk * 8 + laneC4) * 4;
            #pragma unroll
            for (int mt = 0; mt < 4; mt++) {
                uint32_t a = sbase + (uint32_t)((wm * 64 + mt * 16 + laneRow) * GK_ROWU) * 4 + coff;
                ldmat4(ah[mt], a);
                ldmat4(al[mt], a + GK_MATB);
            }
            #pragma unroll
            for (int np = 0; np < 2; np++) {
                uint32_t a = sbase + 2 * GK_MATB
                           + (uint32_t)((wn * 32 + np * 16 + laneRow) * GK_ROWU) * 4 + coff;
                uint32_t tmp[4];
                ldmat4(tmp, a);
                bh[np * 2][0] = tmp[0]; bh[np * 2 + 1][0] = tmp[1];
                bh[np * 2][1] = tmp[2]; bh[np * 2 + 1][1] = tmp[3];
                ldmat4(tmp, a + GK_MATB);
                bl[np * 2][0] = tmp[0]; bl[np * 2 + 1][0] = tmp[1];
                bl[np * 2][1] = tmp[2]; bl[np * 2 + 1][1] = tmp[3];
            }
            #pragma unroll
            for (int mt = 0; mt < 4; mt++)
                #pragma unroll
                for (int nt = 0; nt < 4; nt++) {
                    mma_bf16(acc[mt][nt], ah[mt], bh[nt]);
                    mma_bf16(acc[mt][nt], ah[mt], bl[nt]);
                    mma_bf16(acc[mt][nt], al[mt], bh[nt]);
                }
        }
        __syncthreads();
        issue(c + 3);
    }

    // ---- epilogue ----
    #pragma unroll
    for (int mt = 0; mt < 4; mt++) {
        int row = m0 + wm * 64 + mt * 16 + r0;
        float br0 = 0.f, br1 = 0.f;
        if (BIASMODE == 1) { br0 = bias[row]; br1 = bias[row + 8]; }
        #pragma unroll
        for (int nt = 0; nt < 4; nt++) {
            int col = n0 + wn * 32 + nt * 8 + c0 * 2;
            float v0x = acc[mt][nt][0], v0y = acc[mt][nt][1];
            float v1x = acc[mt][nt][2], v1y = acc[mt][nt][3];
            if (BIASMODE == 1) { v0x += br0; v0y += br0; v1x += br1; v1y += br1; }
            else if (BIASMODE == 2) {
                float bx = bias[col], by = bias[col + 1];
                v0x += bx; v0y += by; v1x += bx; v1y += by;
            }
            size_t o0 = (size_t)b * sC + (size_t)row * ldC + col;
            size_t o1 = (size_t)b * sC + (size_t)(row + 8) * ldC + col;
            if (OUTMODE == 1) {
                split2_store(v0x, v0y, Ch, Cl, o0);
                split2_store(v1x, v1y, Ch, Cl, o1);
            } else {
                if (OUTMODE == 2) {
                    float2 rv0 = *(const float2*)&residg[o0];
                    float2 rv1 = *(const float2*)&residg[o1];
                    v0x += rv0.x; v0y += rv0.y; v1x += rv1.x; v1y += rv1.y;
                }
                *(float2*)&Cf[o0] = make_float2(v0x, v0y);
                *(float2*)&Cf[o1] = make_float2(v1x, v1y);
            }
        }
    }
}

// ---------------- per-(b,c) mean / rstd over 4096 spatial elems -------------
__global__ void __launch_bounds__(256)
stats_kernel(const float* __restrict__ content, const float* __restrict__ style)
{
    int bc  = blockIdx.x;
    int sel = blockIdx.y;
    const float* x = (sel == 0 ? content : style) + (size_t)bc * HW;

    float s1 = 0.f, s2 = 0.f;
    for (int i = threadIdx.x * 4; i < HW; i += 256 * 4) {
        float4 v = *(const float4*)&x[i];
        s1 += v.x + v.y + v.z + v.w;
        s2 += v.x * v.x + v.y * v.y + v.z * v.z + v.w * v.w;
    }
    __shared__ float sh1[8], sh2[8];
    for (int o = 16; o > 0; o >>= 1) {
        s1 += __shfl_xor_sync(0xffffffffu, s1, o);
        s2 += __shfl_xor_sync(0xffffffffu, s2, o);
    }
    int warp = threadIdx.x >> 5, lane = threadIdx.x & 31;
    if (lane == 0) { sh1[warp] = s1; sh2[warp] = s2; }
    __syncthreads();
    if (threadIdx.x < 32) {
        s1 = (lane < 8) ? sh1[lane] : 0.f;
        s2 = (lane < 8) ? sh2[lane] : 0.f;
        for (int o = 4; o > 0; o >>= 1) {
            s1 += __shfl_xor_sync(0xffffffffu, s1, o);
            s2 += __shfl_xor_sync(0xffffffffu, s2, o);
        }
        if (lane == 0) {
            float mean = s1 / (float)HW;
            float var  = (s2 - s1 * mean) / (float)(HW - 1);
            int idx = sel * BATCH * CHN + bc;
            g_mean[idx] = mean;
            g_rstd[idx] = rsqrtf(var + EPSF);
        }
    }
}

// ------- transpose + normalize -> split bf16 planes [b][n][c] --------------
__global__ void __launch_bounds__(256)
transnorm_kernel(const float* __restrict__ content, const float* __restrict__ style,
                 bf16* __restrict__ CNh, bf16* __restrict__ CNl,
                 bf16* __restrict__ SNh, bf16* __restrict__ SNl,
                 bf16* __restrict__ Sth, bf16* __restrict__ Stl)
{
    __shared__ float tc[32][33], ts[32][33];
    int b  = blockIdx.z;
    int c0 = blockIdx.y * 32, n0 = blockIdx.x * 32;
    int t  = threadIdx.x;
    int r  = t >> 3, q = (t & 7) * 4;

    size_t ib = (size_t)b * CHN * HW + (size_t)(c0 + r) * HW + n0 + q;
    float mC = g_mean[b * CHN + c0 + r], rC = g_rstd[b * CHN + c0 + r];
    float4 v = *(const float4*)&content[ib];
    tc[r][q + 0] = (v.x - mC) * rC; tc[r][q + 1] = (v.y - mC) * rC;
    tc[r][q + 2] = (v.z - mC) * rC; tc[r][q + 3] = (v.w - mC) * rC;
    float4 w = *(const float4*)&style[ib];
    ts[r][q + 0] = w.x; ts[r][q + 1] = w.y; ts[r][q + 2] = w.z; ts[r][q + 3] = w.w;
    __syncthreads();

    size_t ob = (size_t)b * CHN * HW + (size_t)(n0 + r) * CHN + c0 + q;
    float ox = tc[q + 0][r], oy = tc[q + 1][r], oz = tc[q + 2][r], ow = tc[q + 3][r];
    split2_store(ox, oy, CNh, CNl, ob);
    split2_store(oz, ow, CNh, CNl, ob + 2);

    float sx = ts[q + 0][r], sy = ts[q + 1][r], sz = ts[q + 2][r], sw = ts[q + 3][r];
    split2_store(sx, sy, Sth, Stl, ob);
    split2_store(sz, sw, Sth, Stl, ob + 2);

    int sidx = BATCH * CHN + b * CHN + c0 + q;
    float4 sm = *(const float4*)&g_mean[sidx];
    float4 sr = *(const float4*)&g_rstd[sidx];
    split2_store((sx - sm.x) * sr.x, (sy - sm.y) * sr.y, SNh, SNl, ob);
    split2_store((sz - sm.z) * sr.z, (sw - sm.w) * sr.w, SNh, SNl, ob + 2);
}

// ---------------- weight split: fp32 [n] -> bf16 hi/lo planes --------------
__global__ void __launch_bounds__(256)
wsplit_kernel(const float* __restrict__ W, bf16* __restrict__ Wh,
              bf16* __restrict__ Wl, int n4)
{
    int i = blockIdx.x * 256 + threadIdx.x;
    if (i < n4) {
        float4 v = *(const float4*)&W[i * 4];
        split2_store(v.x, v.y, Wh, Wl, (size_t)i * 4);
        split2_store(v.z, v.w, Wh, Wl, (size_t)i * 4 + 2);
    }
}

// ------- row softmax over 4096, writes split bf16 P planes -----------------
__global__ void __launch_bounds__(256)
softmax_kernel(const float* __restrict__ S, bf16* __restrict__ Ph,
               bf16* __restrict__ Pl)
{
    __shared__ float buf[HW];
    __shared__ float red1[8], red2[8];
    const float* p = S + (size_t)blockIdx.x * HW;
    size_t ob = (size_t)blockIdx.x * HW;
    int t = threadIdx.x, lane = t & 31, warp = t >> 5;

    float m = -3.4e38f;
    for (int i = t * 4; i < HW; i += 1024) {
        float4 v = *(const float4*)&p[i];
        *(float4*)&buf[i] = v;
        m = fmaxf(m, fmaxf(fmaxf(v.x, v.y), fmaxf(v.z, v.w)));
    }
    for (int o = 16; o > 0; o >>= 1) m = fmaxf(m, __shfl_xor_sync(0xffffffffu, m, o));
    if (lane == 0) red1[warp] = m;
    __syncthreads();
    if (t < 32) {
        m = (lane < 8) ? red1[lane] : -3.4e38f;
        for (int o = 4; o > 0; o >>= 1) m = fmaxf(m, __shfl_xor_sync(0xffffffffu, m, o));
        if (lane == 0) red1[0] = m;
    }
    __syncthreads();
    m = red1[0];

    float s = 0.f;
    for (int i = t * 4; i < HW; i += 1024) {
        float4 v = *(const float4*)&buf[i];
        v.x = __expf(v.x - m); v.y = __expf(v.y - m);
        v.z = __expf(v.z - m); v.w = __expf(v.w - m);
        *(float4*)&buf[i] = v;
        s += v.x + v.y + v.z + v.w;
    }
    for (int o = 16; o > 0; o >>= 1) s += __shfl_xor_sync(0xffffffffu, s, o);
    if (lane == 0) red2[warp] = s;
    __syncthreads();
    if (t < 32) {
        s = (lane < 8) ? red2[lane] : 0.f;
        for (int o = 4; o > 0; o >>= 1) s += __shfl_xor_sync(0xffffffffu, s, o);
        if (lane == 0) red2[0] = s;
    }
    __syncthreads();
    float inv = 1.0f / red2[0];
    for (int i = t * 4; i < HW; i += 1024) {
        float4 v = *(const float4*)&buf[i];
        v.x *= inv; v.y *= inv; v.z *= inv; v.w *= inv;
        split2_store(v.x, v.y, Ph, Pl, ob + i);
        split2_store(v.z, v.w, Ph, Pl, ob + i + 2);
    }
}

// ---------------- launch --------------------------------------------------
extern "C" void kernel_launch(void* const* d_in, const int* in_sizes, int n_in,
                              void* d_out, int out_size)
{
    const float* content = (const float*)d_in[0];
    const float* style   = (const float*)d_in[1];
    const float* Wf = (const float*)d_in[2]; const float* bf = (const float*)d_in[3];
    const float* Wg = (const float*)d_in[4]; const float* bg = (const float*)d_in[5];
    const float* Wh = (const float*)d_in[6]; const float* bh = (const float*)d_in[7];
    const float* Wo = (const float*)d_in[8]; const float* bo = (const float*)d_in[9];
    float* out = (float*)d_out;

    bf16 *pCNh, *pCNl, *pSNh, *pSNl, *pSth, *pStl;
    bf16 *pFh, *pFl, *pGh, *pGl, *pHh, *pHl, *pOh, *pOl, *pPh, *pPl;
    bf16 *pWfh, *pWfl, *pWgh, *pWgl, *pWhh, *pWhl, *pWoh, *pWol;
    float *pS;
    cudaGetSymbolAddress((void**)&pCNh, g_CN_h); cudaGetSymbolAddress((void**)&pCNl, g_CN_l);
    cudaGetSymbolAddress((void**)&pSNh, g_SN_h); cudaGetSymbolAddress((void**)&pSNl, g_SN_l);
    cudaGetSymbolAddress((void**)&pSth, g_St_h); cudaGetSymbolAddress((void**)&pStl, g_St_l);
    cudaGetSymbolAddress((void**)&pFh, g_F_h);   cudaGetSymbolAddress((void**)&pFl, g_F_l);
    cudaGetSymbolAddress((void**)&pGh, g_G_h);   cudaGetSymbolAddress((void**)&pGl, g_G_l);
    cudaGetSymbolAddress((void**)&pHh, g_H_h);   cudaGetSymbolAddress((void**)&pHl, g_H_l);
    cudaGetSymbolAddress((void**)&pOh, g_O_h);   cudaGetSymbolAddress((void**)&pOl, g_O_l);
    cudaGetSymbolAddress((void**)&pPh, g_P_h);   cudaGetSymbolAddress((void**)&pPl, g_P_l);
    cudaGetSymbolAddress((void**)&pWfh, g_Wf_h); cudaGetSymbolAddress((void**)&pWfl, g_Wf_l);
    cudaGetSymbolAddress((void**)&pWgh, g_Wg_h); cudaGetSymbolAddress((void**)&pWgl, g_Wg_l);
    cudaGetSymbolAddress((void**)&pWhh, g_Wh_h); cudaGetSymbolAddress((void**)&pWhl, g_Wh_l);
    cudaGetSymbolAddress((void**)&pWoh, g_Wo_h); cudaGetSymbolAddress((void**)&pWol, g_Wo_l);
    cudaGetSymbolAddress((void**)&pS, g_S);

    cudaFuncSetAttribute(gemm2<2, 1>, cudaFuncAttributeMaxDynamicSharedMemorySize, GK_SMEMB);
    cudaFuncSetAttribute(gemm2<1, 1>, cudaFuncAttributeMaxDynamicSharedMemorySize, GK_SMEMB);
    cudaFuncSetAttribute(gemm2<0, 0>, cudaFuncAttributeMaxDynamicSharedMemorySize, GK_SMEMB);
    cudaFuncSetAttribute(gemm2<0, 1>, cudaFuncAttributeMaxDynamicSharedMemorySize, GK_SMEMB);
    cudaFuncSetAttribute(gemm2<1, 2>, cudaFuncAttributeMaxDynamicSharedMemorySize, GK_SMEMB);

    const size_t sBCHW = (size_t)CHN * HW;
    const size_t sBHH  = (size_t)HW * HW;

    // 1) stats + weight splits + transpose/normalize splits
    stats_kernel<<<dim3(BATCH * CHN, 2), 256>>>(content, style);
    wsplit_kernel<<<(CHN * CHN / 4 + 255) / 256, 256>>>(Wf, pWfh, pWfl, CHN * CHN / 4);
    wsplit_kernel<<<(CHN * CHN / 4 + 255) / 256, 256>>>(Wg, pWgh, pWgl, CHN * CHN / 4);
    wsplit_kernel<<<(CHN * CHN / 4 + 255) / 256, 256>>>(Wh, pWhh, pWhl, CHN * CHN / 4);
    wsplit_kernel<<<(CHN * CHN / 4 + 255) / 256, 256>>>(Wo, pWoh, pWol, CHN * CHN / 4);
    transnorm_kernel<<<dim3(HW / 32, CHN / 32, BATCH), 256>>>(
        content, style, pCNh, pCNl, pSNh, pSNl, pSth, pStl);

    // 2) F_t[n,c] = CN_t[n,:] . Wf[c,:]   (bias per col, split out)
    gemm2<2, 1><<<dim3(CHN / 128, HW / 128, BATCH), 256, GK_SMEMB>>>(
        pCNh, pCNl, pWfh, pWfl, bf, nullptr, nullptr, pFh, pFl,
        CHN, CHN, CHN, CHN, sBCHW, 0, sBCHW);

    // 3) G_t[n,c] = SN_t[n,:] . Wg[c,:]
    gemm2<2, 1><<<dim3(CHN / 128, HW / 128, BATCH), 256, GK_SMEMB>>>(
        pSNh, pSNl, pWgh, pWgl, bg, nullptr, nullptr, pGh, pGl,
        CHN, CHN, CHN, CHN, sBCHW, 0, sBCHW);

    // 4) H[c,m] = Wh[c,:] . St[m,:]       (bias per row, split out)
    gemm2<1, 1><<<dim3(HW / 128, CHN / 128, BATCH), 256, GK_SMEMB>>>(
        pWhh, pWhl, pSth, pStl, bh, nullptr, nullptr, pHh, pHl,
        CHN, CHN, CHN, HW, 0, sBCHW, sBCHW);

    // 5) S[n,m] = F_t[n,:] . G_t[m,:]     (fp32 out)
    gemm2<0, 0><<<dim3(HW / 128, HW / 128, BATCH), 256, GK_SMEMB>>>(
        pFh, pFl, pGh, pGl, nullptr, nullptr, pS, nullptr, nullptr,
        CHN, CHN, CHN, HW, sBCHW, sBCHW, sBHH);

    // 6) softmax rows of S -> split bf16 P
    softmax_kernel<<<BATCH * HW, 256>>>(pS, pPh, pPl);

    // 7) O_t[n,c] = P[n,:] . H[c,:]       (K = HW, split out)
    gemm2<0, 1><<<dim3(CHN / 128, HW / 128, BATCH), 256, GK_SMEMB>>>(
        pPh, pPl, pHh, pHl, nullptr, nullptr, nullptr, pOh, pOl,
        HW, HW, HW, CHN, sBHH, sBCHW, sBCHW);

    // 8) out[c,n] = Wo[c,:] . O_t[n,:] + bo + content
    gemm2<1, 2><<<dim3(HW / 128, CHN / 128, BATCH), 256, GK_SMEMB>>>(
        pWoh, pWol, pOh, pOl, bo, content, out, nullptr, nullptr,
        CHN, CHN, CHN, HW, 0, sBCHW, sBCHW);
}

// round 7
// speedup vs baseline: 1.1504x; 1.1504x over previous
#include <cuda_runtime.h>
#include <cstdint>
#include <math.h>

#define BATCH 4
#define CHN   512
#define HW    4096
#define EPSF  1e-5f

// ---------------- scratch (device globals; no allocations allowed) ----------
__device__ float g_CNt[BATCH * CHN * HW];               // norm(content)^T [b][n][c]
__device__ float g_SNt[BATCH * CHN * HW];               // norm(style)^T   [b][n][c]
__device__ float g_St [BATCH * CHN * HW];               // style^T         [b][n][c]
__device__ float g_F[BATCH * CHN * HW];                 // F_t [b][n][c]
__device__ float g_G[BATCH * CHN * HW];                 // G_t [b][n][c]
__device__ float g_H[BATCH * CHN * HW];                 // H   [b][c][m]
__device__ float g_O[BATCH * CHN * HW];                 // O_t [b][n][c]
__device__ float g_S[(size_t)BATCH * HW * HW];          // S   [b][n][m]
__device__ float g_mean[2 * BATCH * CHN];
__device__ float g_rstd[2 * BATCH * CHN];

// ============================ helpers =======================================
__device__ __forceinline__ uint32_t pack_bf16x2(float lo, float hi) {
    uint32_t r;
    asm("cvt.rn.bf16x2.f32 %0, %1, %2;" : "=r"(r) : "f"(hi), "f"(lo));
    return r;
}

__device__ __forceinline__ void mma_bf16(float* d, const uint32_t* a, const uint32_t* b) {
    asm volatile(
        "mma.sync.aligned.m16n8k16.row.col.f32.bf16.bf16.f32 "
        "{%0,%1,%2,%3}, {%4,%5,%6,%7}, {%8,%9}, {%0,%1,%2,%3};"
        : "+f"(d[0]), "+f"(d[1]), "+f"(d[2]), "+f"(d[3])
        : "r"(a[0]), "r"(a[1]), "r"(a[2]), "r"(a[3]), "r"(b[0]), "r"(b[1]));
}

// split one float4 into packed bf16x2 hi/lo pairs (pairs along k)
__device__ __forceinline__ void split4(float4 v, uint32_t& h0, uint32_t& h1,
                                       uint32_t& l0, uint32_t& l1) {
    h0 = pack_bf16x2(v.x, v.y);
    h1 = pack_bf16x2(v.z, v.w);
    float hx = __uint_as_float(h0 << 16);
    float hy = __uint_as_float(h0 & 0xffff0000u);
    float hz = __uint_as_float(h1 << 16);
    float hw = __uint_as_float(h1 & 0xffff0000u);
    l0 = pack_bf16x2(v.x - hx, v.y - hy);
    l1 = pack_bf16x2(v.z - hz, v.w - hw);
}

// =================== bf16 3-split mma GEMM (NT), 512 threads ================
// D[m,n] = sum_k A[m,k]*B[n,k]. A:[M,K] rm, B:[N,K] rm, C:[M,N] rm.
// K % 32 == 0. 128x128 CTA tile, 16 warps (4x4), warp tile 32x32, BK=32,
// double-buffered smem, ONE barrier per chunk, producer overlapped with mma.
// BIASMODE: 0=none, 1=bias[m], 2=bias[n]
#define BGK_ROW   20
#define BGK_MAT   (128 * BGK_ROW)
#define BGK_STAGE (4 * BGK_MAT)
#define BGK_SMEMB (2 * BGK_STAGE * 4)            // 81920 bytes

template<int BIASMODE, bool RESID>
__global__ void __launch_bounds__(512, 1)
bf16_gemm_kernel(const float* __restrict__ Ag, const float* __restrict__ Bg,
                 const float* __restrict__ bias, const float* __restrict__ residg,
                 float* __restrict__ Cg, int K, int ldA, int ldB, int ldC,
                 size_t sA, size_t sB, size_t sC)
{
    extern __shared__ uint32_t smem_u32[];

    const int t    = threadIdx.x;
    const int lane = t & 31;
    const int wid  = t >> 5;
    const int wm   = wid >> 2;          // 0..3 (32-row band)
    const int wn   = wid & 3;           // 0..3 (32-col band)
    const int r0   = lane >> 2;         // 0..7
    const int c0   = lane & 3;          // 0..3

    const int b  = blockIdx.z;
    const int m0 = blockIdx.y * 128, n0 = blockIdx.x * 128;
    const float* A = Ag + (size_t)b * sA + (size_t)m0 * ldA;
    const float* B = Bg + (size_t)b * sB + (size_t)n0 * ldB;
    float*       C = Cg + (size_t)b * sC;

    const int NC = K >> 5;
    const int lrow = t >> 2;            // 0..127
    const int lq4  = (t & 3) * 2;       // float4 chunk index (0,2,4,6)

    float4 va[2], vb[2];

    auto gload = [&](int c) {
        const int k0 = c << 5;
        #pragma unroll
        for (int j = 0; j < 2; j++) {
            va[j] = *(const float4*)&A[(size_t)lrow * ldA + k0 + (lq4 + j) * 4];
            vb[j] = *(const float4*)&B[(size_t)lrow * ldB + k0 + (lq4 + j) * 4];
        }
    };
    auto sstore = [&](int s) {
        uint32_t* base = smem_u32 + s * BGK_STAGE;
        #pragma unroll
        for (int j = 0; j < 2; j++) {
            uint32_t off = lrow * BGK_ROW + (lq4 + j) * 2;
            uint32_t h0, h1, l0, l1;
            split4(va[j], h0, h1, l0, l1);
            base[off] = h0; base[off + 1] = h1;
            base[BGK_MAT + off] = l0; base[BGK_MAT + off + 1] = l1;
            split4(vb[j], h0, h1, l0, l1);
            base[2 * BGK_MAT + off] = h0; base[2 * BGK_MAT + off + 1] = h1;
            base[3 * BGK_MAT + off] = l0; base[3 * BGK_MAT + off + 1] = l1;
        }
    };

    float acc[2][4][4] = {};

    gload(0);
    sstore(0);
    if (NC > 1) gload(1);
    __syncthreads();

    for (int c = 0; c < NC; c++) {
        const int s = c & 1;
        const uint32_t* sa_h = smem_u32 + s * BGK_STAGE;
        const uint32_t* sa_l = sa_h + BGK_MAT;
        const uint32_t* sb_h = sa_h + 2 * BGK_MAT;
        const uint32_t* sb_l = sa_h + 3 * BGK_MAT;

        #pragma unroll
        for (int kk = 0; kk < 2; kk++) {
            uint32_t ah[2][4], al[2][4], bh[4][2], bl[4][2];
            const int cA = kk * 8 + c0;
            #pragma unroll
            for (int mt = 0; mt < 2; mt++) {
                int r = wm * 32 + mt * 16 + r0;
                const uint32_t* ph = &sa_h[r * BGK_ROW + cA];
                const uint32_t* pl = &sa_l[r * BGK_ROW + cA];
                ah[mt][0] = ph[0]; ah[mt][1] = ph[8 * BGK_ROW];
                ah[mt][2] = ph[4]; ah[mt][3] = ph[8 * BGK_ROW + 4];
                al[mt][0] = pl[0]; al[mt][1] = pl[8 * BGK_ROW];
                al[mt][2] = pl[4]; al[mt][3] = pl[8 * BGK_ROW + 4];
            }
            #pragma unroll
            for (int nt = 0; nt < 4; nt++) {
                int n = wn * 32 + nt * 8 + r0;
                bh[nt][0] = sb_h[n * BGK_ROW + cA]; bh[nt][1] = sb_h[n * BGK_ROW + cA + 4];
                bl[nt][0] = sb_l[n * BGK_ROW + cA]; bl[nt][1] = sb_l[n * BGK_ROW + cA + 4];
            }

            // overlap producer work with the mma stream
            if (kk == 0) { if (c + 1 < NC) sstore((c + 1) & 1); }
            else         { if (c + 2 < NC) gload(c + 2); }

            #pragma unroll
            for (int mt = 0; mt < 2; mt++)
                #pragma unroll
                for (int nt = 0; nt < 4; nt++) {
                    mma_bf16(acc[mt][nt], ah[mt], bh[nt]);
                    mma_bf16(acc[mt][nt], ah[mt], bl[nt]);
                    mma_bf16(acc[mt][nt], al[mt], bh[nt]);
                }
        }
        __syncthreads();   // single barrier per chunk
    }

    // ---- epilogue ----
    #pragma unroll
    for (int mt = 0; mt < 2; mt++) {
        int row = m0 + wm * 32 + mt * 16 + r0;
        float br0 = 0.f, br1 = 0.f;
        if (BIASMODE == 1) { br0 = bias[row]; br1 = bias[row + 8]; }
        #pragma unroll
        for (int nt = 0; nt < 4; nt++) {
            int col = n0 + wn * 32 + nt * 8 + c0 * 2;
            float2 v0 = make_float2(acc[mt][nt][0], acc[mt][nt][1]);
            float2 v1 = make_float2(acc[mt][nt][2], acc[mt][nt][3]);
            if (BIASMODE == 1) {
                v0.x += br0; v0.y += br0;
                v1.x += br1; v1.y += br1;
            } else if (BIASMODE == 2) {
                float bx = bias[col], by = bias[col + 1];
                v0.x += bx; v0.y += by;
                v1.x += bx; v1.y += by;
            }
            if (RESID) {
                float2 rv0 = *(const float2*)&residg[(size_t)b * sC + (size_t)row * ldC + col];
                float2 rv1 = *(const float2*)&residg[(size_t)b * sC + (size_t)(row + 8) * ldC + col];
                v0.x += rv0.x; v0.y += rv0.y;
                v1.x += rv1.x; v1.y += rv1.y;
            }
            *(float2*)&C[(size_t)row * ldC + col]       = v0;
            *(float2*)&C[(size_t)(row + 8) * ldC + col] = v1;
        }
    }
}

// ---------------- per-(b,c) mean / rstd over 4096 spatial elems -------------
__global__ void __launch_bounds__(256)
stats_kernel(const float* __restrict__ content, const float* __restrict__ style)
{
    int bc  = blockIdx.x;
    int sel = blockIdx.y;
    const float* x = (sel == 0 ? content : style) + (size_t)bc * HW;

    float s1 = 0.f, s2 = 0.f;
    for (int i = threadIdx.x * 4; i < HW; i += 256 * 4) {
        float4 v = *(const float4*)&x[i];
        s1 += v.x + v.y + v.z + v.w;
        s2 += v.x * v.x + v.y * v.y + v.z * v.z + v.w * v.w;
    }
    __shared__ float sh1[8], sh2[8];
    for (int o = 16; o > 0; o >>= 1) {
        s1 += __shfl_xor_sync(0xffffffffu, s1, o);
        s2 += __shfl_xor_sync(0xffffffffu, s2, o);
    }
    int warp = threadIdx.x >> 5, lane = threadIdx.x & 31;
    if (lane == 0) { sh1[warp] = s1; sh2[warp] = s2; }
    __syncthreads();
    if (threadIdx.x < 32) {
        s1 = (lane < 8) ? sh1[lane] : 0.f;
        s2 = (lane < 8) ? sh2[lane] : 0.f;
        for (int o = 4; o > 0; o >>= 1) {
            s1 += __shfl_xor_sync(0xffffffffu, s1, o);
            s2 += __shfl_xor_sync(0xffffffffu, s2, o);
        }
        if (lane == 0) {
            float mean = s1 / (float)HW;
            float var  = (s2 - s1 * mean) / (float)(HW - 1);
            int idx = sel * BATCH * CHN + bc;
            g_mean[idx] = mean;
            g_rstd[idx] = rsqrtf(var + EPSF);
        }
    }
}

// ------- transpose + normalize: [b][c][n] -> [b][n][c], 3 outputs ----------
__global__ void __launch_bounds__(256)
transnorm_kernel(const float* __restrict__ content, const float* __restrict__ style,
                 float* __restrict__ CNt, float* __restrict__ SNt,
                 float* __restrict__ St)
{
    __shared__ float tc[32][33], ts[32][33];
    int b  = blockIdx.z;
    int c0 = blockIdx.y * 32, n0 = blockIdx.x * 32;
    int t  = threadIdx.x;
    int r  = t >> 3, q = (t & 7) * 4;

    size_t ib = (size_t)b * CHN * HW + (size_t)(c0 + r) * HW + n0 + q;
    float mC = g_mean[b * CHN + c0 + r], rC = g_rstd[b * CHN + c0 + r];
    float4 v = *(const float4*)&content[ib];
    tc[r][q + 0] = (v.x - mC) * rC; tc[r][q + 1] = (v.y - mC) * rC;
    tc[r][q + 2] = (v.z - mC) * rC; tc[r][q + 3] = (v.w - mC) * rC;
    float4 w = *(const float4*)&style[ib];
    ts[r][q + 0] = w.x; ts[r][q + 1] = w.y; ts[r][q + 2] = w.z; ts[r][q + 3] = w.w;
    __syncthreads();

    size_t ob = (size_t)b * CHN * HW + (size_t)(n0 + r) * CHN + c0 + q;
    float4 o;
    o.x = tc[q + 0][r]; o.y = tc[q + 1][r]; o.z = tc[q + 2][r]; o.w = tc[q + 3][r];
    *(float4*)&CNt[ob] = o;

    float4 sraw;
    sraw.x = ts[q + 0][r]; sraw.y = ts[q + 1][r];
    sraw.z = ts[q + 2][r]; sraw.w = ts[q + 3][r];
    *(float4*)&St[ob] = sraw;

    int sidx = BATCH * CHN + b * CHN + c0 + q;
    float4 sm = *(const float4*)&g_mean[sidx];
    float4 sr = *(const float4*)&g_rstd[sidx];
    float4 sn;
    sn.x = (sraw.x - sm.x) * sr.x; sn.y = (sraw.y - sm.y) * sr.y;
    sn.z = (sraw.z - sm.z) * sr.z; sn.w = (sraw.w - sm.w) * sr.w;
    *(float4*)&SNt[ob] = sn;
}

// ---------------- row softmax over 4096, row cached in smem -----------------
__global__ void __launch_bounds__(256)
softmax_kernel(float* __restrict__ S)
{
    __shared__ float buf[HW];
    __shared__ float red1[8], red2[8];
    float* p = S + (size_t)blockIdx.x * HW;
    int t = threadIdx.x, lane = t & 31, warp = t >> 5;

    float m = -3.4e38f;
    for (int i = t * 4; i < HW; i += 1024) {
        float4 v = *(const float4*)&p[i];
        *(float4*)&buf[i] = v;
        m = fmaxf(m, fmaxf(fmaxf(v.x, v.y), fmaxf(v.z, v.w)));
    }
    for (int o = 16; o > 0; o >>= 1) m = fmaxf(m, __shfl_xor_sync(0xffffffffu, m, o));
    if (lane == 0) red1[warp] = m;
    __syncthreads();
    if (t < 32) {
        m = (lane < 8) ? red1[lane] : -3.4e38f;
        for (int o = 4; o > 0; o >>= 1) m = fmaxf(m, __shfl_xor_sync(0xffffffffu, m, o));
        if (lane == 0) red1[0] = m;
    }
    __syncthreads();
    m = red1[0];

    float s = 0.f;
    for (int i = t * 4; i < HW; i += 1024) {
        float4 v = *(const float4*)&buf[i];
        v.x = __expf(v.x - m); v.y = __expf(v.y - m);
        v.z = __expf(v.z - m); v.w = __expf(v.w - m);
        *(float4*)&buf[i] = v;
        s += v.x + v.y + v.z + v.w;
    }
    for (int o = 16; o > 0; o >>= 1) s += __shfl_xor_sync(0xffffffffu, s, o);
    if (lane == 0) red2[warp] = s;
    __syncthreads();
    if (t < 32) {
        s = (lane < 8) ? red2[lane] : 0.f;
        for (int o = 4; o > 0; o >>= 1) s += __shfl_xor_sync(0xffffffffu, s, o);
        if (lane == 0) red2[0] = s;
    }
    __syncthreads();
    float inv = 1.0f / red2[0];
    for (int i = t * 4; i < HW; i += 1024) {
        float4 v = *(const float4*)&buf[i];
        v.x *= inv; v.y *= inv; v.z *= inv; v.w *= inv;
        *(float4*)&p[i] = v;
    }
}

// ---------------- launch --------------------------------------------------
extern "C" void kernel_launch(void* const* d_in, const int* in_sizes, int n_in,
                              void* d_out, int out_size)
{
    const float* content = (const float*)d_in[0];
    const float* style   = (const float*)d_in[1];
    const float* Wf = (const float*)d_in[2]; const float* bf = (const float*)d_in[3];
    const float* Wg = (const float*)d_in[4]; const float* bg = (const float*)d_in[5];
    const float* Wh = (const float*)d_in[6]; const float* bh = (const float*)d_in[7];
    const float* Wo = (const float*)d_in[8]; const float* bo = (const float*)d_in[9];
    float* out = (float*)d_out;

    float *pCNt, *pSNt, *pSt, *pF, *pG, *pH, *pO, *pS;
    cudaGetSymbolAddress((void**)&pCNt, g_CNt);
    cudaGetSymbolAddress((void**)&pSNt, g_SNt);
    cudaGetSymbolAddress((void**)&pSt,  g_St);
    cudaGetSymbolAddress((void**)&pF, g_F);
    cudaGetSymbolAddress((void**)&pG, g_G);
    cudaGetSymbolAddress((void**)&pH, g_H);
    cudaGetSymbolAddress((void**)&pO, g_O);
    cudaGetSymbolAddress((void**)&pS, g_S);

    cudaFuncSetAttribute(bf16_gemm_kernel<0, false>,
                         cudaFuncAttributeMaxDynamicSharedMemorySize, BGK_SMEMB);
    cudaFuncSetAttribute(bf16_gemm_kernel<1, false>,
                         cudaFuncAttributeMaxDynamicSharedMemorySize, BGK_SMEMB);
    cudaFuncSetAttribute(bf16_gemm_kernel<2, false>,
                         cudaFuncAttributeMaxDynamicSharedMemorySize, BGK_SMEMB);
    cudaFuncSetAttribute(bf16_gemm_kernel<1, true>,
                         cudaFuncAttributeMaxDynamicSharedMemorySize, BGK_SMEMB);

    const size_t sBCHW = (size_t)CHN * HW;
    const size_t sBHH  = (size_t)HW * HW;

    // 1) normalization stats
    stats_kernel<<<dim3(BATCH * CHN, 2), 256>>>(content, style);

    // 2) transpose + normalize: CN_t, SN_t, St  ([b][n][c])
    transnorm_kernel<<<dim3(HW / 32, CHN / 32, BATCH), 256>>>(
        content, style, pCNt, pSNt, pSt);

    // 3) F_t[n,c] = CN_t[n,:] . Wf[c,:]   (bias per col)
    bf16_gemm_kernel<2, false><<<dim3(CHN / 128, HW / 128, BATCH), 512, BGK_SMEMB>>>(
        pCNt, Wf, bf, nullptr, pF, CHN, CHN, CHN, CHN, sBCHW, 0, sBCHW);

    // 4) G_t[n,c] = SN_t[n,:] . Wg[c,:]   (bias per col)
    bf16_gemm_kernel<2, false><<<dim3(CHN / 128, HW / 128, BATCH), 512, BGK_SMEMB>>>(
        pSNt, Wg, bg, nullptr, pG, CHN, CHN, CHN, CHN, sBCHW, 0, sBCHW);

    // 5) H[c,m] = Wh[c,:] . St[m,:]       (bias per row)
    bf16_gemm_kernel<1, false><<<dim3(HW / 128, CHN / 128, BATCH), 512, BGK_SMEMB>>>(
        Wh, pSt, bh, nullptr, pH, CHN, CHN, CHN, HW, 0, sBCHW, sBCHW);

    // 6) S[n,m] = F_t[n,:] . G_t[m,:]
    bf16_gemm_kernel<0, false><<<dim3(HW / 128, HW / 128, BATCH), 512, BGK_SMEMB>>>(
        pF, pG, nullptr, nullptr, pS, CHN, CHN, CHN, HW,
        sBCHW, sBCHW, sBHH);

    // 7) softmax rows of S
    softmax_kernel<<<BATCH * HW, 256>>>(pS);

    // 8) O_t[n,c] = P[n,:] . H[c,:]       (K = HW)
    bf16_gemm_kernel<0, false><<<dim3(CHN / 128, HW / 128, BATCH), 512, BGK_SMEMB>>>(
        pS, pH, nullptr, nullptr, pO, HW, HW, HW, CHN,
        sBHH, sBCHW, sBCHW);

    // 9) out[c,n] = Wo[c,:] . O_t[n,:] + bo + content   (bias per row + resid)
    bf16_gemm_kernel<1, true><<<dim3(HW / 128, CHN / 128, BATCH), 512, BGK_SMEMB>>>(
        Wo, pO, bo, content, out, CHN, CHN, CHN, HW, 0, sBCHW, sBCHW);
}

// round 8
// speedup vs baseline: 1.1533x; 1.0025x over previous
#include <cuda_runtime.h>
#include <cstdint>
#include <math.h>

#define BATCH 4
#define CHN   512
#define HW    4096
#define EPSF  1e-5f

// ---------------- scratch (device globals; no allocations allowed) ----------
__device__ float g_CNt[BATCH * CHN * HW];               // norm(content)^T [b][n][c]
__device__ float g_SNt[BATCH * CHN * HW];               // norm(style)^T   [b][n][c]
__device__ float g_St [BATCH * CHN * HW];               // style^T         [b][n][c]
__device__ float g_F[BATCH * CHN * HW];                 // F_t [b][n][c]
__device__ float g_G[BATCH * CHN * HW];                 // G_t [b][n][c]
__device__ float g_H[BATCH * CHN * HW];                 // H   [b][c][m]
__device__ float g_O[BATCH * CHN * HW];                 // O_t [b][n][c]
__device__ float g_S[(size_t)BATCH * HW * HW];          // S   [b][n][m]
__device__ float g_mean[2 * BATCH * CHN];
__device__ float g_rstd[2 * BATCH * CHN];

// ============================ helpers =======================================
__device__ __forceinline__ uint32_t pack_bf16x2(float lo, float hi) {
    uint32_t r;
    asm("cvt.rn.bf16x2.f32 %0, %1, %2;" : "=r"(r) : "f"(hi), "f"(lo));
    return r;
}

__device__ __forceinline__ void mma_bf16(float* d, const uint32_t* a, const uint32_t* b) {
    asm volatile(
        "mma.sync.aligned.m16n8k16.row.col.f32.bf16.bf16.f32 "
        "{%0,%1,%2,%3}, {%4,%5,%6,%7}, {%8,%9}, {%0,%1,%2,%3};"
        : "+f"(d[0]), "+f"(d[1]), "+f"(d[2]), "+f"(d[3])
        : "r"(a[0]), "r"(a[1]), "r"(a[2]), "r"(a[3]), "r"(b[0]), "r"(b[1]));
}

// split one float4 into packed bf16x2 hi/lo pairs (pairs along k)
__device__ __forceinline__ void split4(float4 v, uint32_t& h0, uint32_t& h1,
                                       uint32_t& l0, uint32_t& l1) {
    h0 = pack_bf16x2(v.x, v.y);
    h1 = pack_bf16x2(v.z, v.w);
    float hx = __uint_as_float(h0 << 16);
    float hy = __uint_as_float(h0 & 0xffff0000u);
    float hz = __uint_as_float(h1 << 16);
    float hw = __uint_as_float(h1 & 0xffff0000u);
    l0 = pack_bf16x2(v.x - hx, v.y - hy);
    l1 = pack_bf16x2(v.z - hz, v.w - hw);
}

// =================== bf16 3-split mma GEMM (NT), 512 threads ================
// D[m,n] = sum_k A[m,k]*B[n,k]. A:[M,K] rm, B:[N,K] rm, C:[M,N] rm.
// K % 32 == 0. 128x128 CTA tile, 16 warps (4x4), warp tile 32x32, BK=32,
// double-buffered smem, ONE barrier per chunk, producer overlapped with mma.
// MMAs issued TERM-MAJOR so consecutive MMAs hit different accumulators.
// BIASMODE: 0=none, 1=bias[m], 2=bias[n]
#define BGK_ROW   20
#define BGK_MAT   (128 * BGK_ROW)
#define BGK_STAGE (4 * BGK_MAT)
#define BGK_SMEMB (2 * BGK_STAGE * 4)            // 81920 bytes

template<int BIASMODE, bool RESID>
__global__ void __launch_bounds__(512, 1)
bf16_gemm_kernel(const float* __restrict__ Ag, const float* __restrict__ Bg,
                 const float* __restrict__ bias, const float* __restrict__ residg,
                 float* __restrict__ Cg, int K, int ldA, int ldB, int ldC,
                 size_t sA, size_t sB, size_t sC)
{
    extern __shared__ uint32_t smem_u32[];

    const int t    = threadIdx.x;
    const int lane = t & 31;
    const int wid  = t >> 5;
    const int wm   = wid >> 2;          // 0..3 (32-row band)
    const int wn   = wid & 3;           // 0..3 (32-col band)
    const int r0   = lane >> 2;         // 0..7
    const int c0   = lane & 3;          // 0..3

    const int b  = blockIdx.z;
    const int m0 = blockIdx.y * 128, n0 = blockIdx.x * 128;
    const float* A = Ag + (size_t)b * sA + (size_t)m0 * ldA;
    const float* B = Bg + (size_t)b * sB + (size_t)n0 * ldB;
    float*       C = Cg + (size_t)b * sC;

    const int NC = K >> 5;
    const int lrow = t >> 2;            // 0..127
    const int lq4  = (t & 3) * 2;       // float4 chunk index (0,2,4,6)

    float4 va[2], vb[2];

    auto gload = [&](int c) {
        const int k0 = c << 5;
        #pragma unroll
        for (int j = 0; j < 2; j++) {
            va[j] = *(const float4*)&A[(size_t)lrow * ldA + k0 + (lq4 + j) * 4];
            vb[j] = *(const float4*)&B[(size_t)lrow * ldB + k0 + (lq4 + j) * 4];
        }
    };
    auto sstore = [&](int s) {
        uint32_t* base = smem_u32 + s * BGK_STAGE;
        #pragma unroll
        for (int j = 0; j < 2; j++) {
            uint32_t off = lrow * BGK_ROW + (lq4 + j) * 2;
            uint32_t h0, h1, l0, l1;
            split4(va[j], h0, h1, l0, l1);
            base[off] = h0; base[off + 1] = h1;
            base[BGK_MAT + off] = l0; base[BGK_MAT + off + 1] = l1;
            split4(vb[j], h0, h1, l0, l1);
            base[2 * BGK_MAT + off] = h0; base[2 * BGK_MAT + off + 1] = h1;
            base[3 * BGK_MAT + off] = l0; base[3 * BGK_MAT + off + 1] = l1;
        }
    };

    float acc[2][4][4] = {};

    gload(0);
    sstore(0);
    if (NC > 1) gload(1);
    __syncthreads();

    for (int c = 0; c < NC; c++) {
        const int s = c & 1;
        const uint32_t* sa_h = smem_u32 + s * BGK_STAGE;
        const uint32_t* sa_l = sa_h + BGK_MAT;
        const uint32_t* sb_h = sa_h + 2 * BGK_MAT;
        const uint32_t* sb_l = sa_h + 3 * BGK_MAT;

        #pragma unroll
        for (int kk = 0; kk < 2; kk++) {
            uint32_t ah[2][4], al[2][4], bh[4][2], bl[4][2];
            const int cA = kk * 8 + c0;
            #pragma unroll
            for (int mt = 0; mt < 2; mt++) {
                int r = wm * 32 + mt * 16 + r0;
                const uint32_t* ph = &sa_h[r * BGK_ROW + cA];
                const uint32_t* pl = &sa_l[r * BGK_ROW + cA];
                ah[mt][0] = ph[0]; ah[mt][1] = ph[8 * BGK_ROW];
                ah[mt][2] = ph[4]; ah[mt][3] = ph[8 * BGK_ROW + 4];
                al[mt][0] = pl[0]; al[mt][1] = pl[8 * BGK_ROW];
                al[mt][2] = pl[4]; al[mt][3] = pl[8 * BGK_ROW + 4];
            }
            #pragma unroll
            for (int nt = 0; nt < 4; nt++) {
                int n = wn * 32 + nt * 8 + r0;
                bh[nt][0] = sb_h[n * BGK_ROW + cA]; bh[nt][1] = sb_h[n * BGK_ROW + cA + 4];
                bl[nt][0] = sb_l[n * BGK_ROW + cA]; bl[nt][1] = sb_l[n * BGK_ROW + cA + 4];
            }

            // overlap producer work with the mma stream
            if (kk == 0) { if (c + 1 < NC) sstore((c + 1) & 1); }
            else         { if (c + 2 < NC) gload(c + 2); }

            // term-major: consecutive MMAs target different accumulators,
            // per-acc order stays hh -> hl -> lh (numerics unchanged)
            #pragma unroll
            for (int mt = 0; mt < 2; mt++)
                #pragma unroll
                for (int nt = 0; nt < 4; nt++)
                    mma_bf16(acc[mt][nt], ah[mt], bh[nt]);
            #pragma unroll
            for (int mt = 0; mt < 2; mt++)
                #pragma unroll
                for (int nt = 0; nt < 4; nt++)
                    mma_bf16(acc[mt][nt], ah[mt], bl[nt]);
            #pragma unroll
            for (int mt = 0; mt < 2; mt++)
                #pragma unroll
                for (int nt = 0; nt < 4; nt++)
                    mma_bf16(acc[mt][nt], al[mt], bh[nt]);
        }
        __syncthreads();   // single barrier per chunk
    }

    // ---- epilogue ----
    #pragma unroll
    for (int mt = 0; mt < 2; mt++) {
        int row = m0 + wm * 32 + mt * 16 + r0;
        float br0 = 0.f, br1 = 0.f;
        if (BIASMODE == 1) { br0 = bias[row]; br1 = bias[row + 8]; }
        #pragma unroll
        for (int nt = 0; nt < 4; nt++) {
            int col = n0 + wn * 32 + nt * 8 + c0 * 2;
            float2 v0 = make_float2(acc[mt][nt][0], acc[mt][nt][1]);
            float2 v1 = make_float2(acc[mt][nt][2], acc[mt][nt][3]);
            if (BIASMODE == 1) {
                v0.x += br0; v0.y += br0;
                v1.x += br1; v1.y += br1;
            } else if (BIASMODE == 2) {
                float bx = bias[col], by = bias[col + 1];
                v0.x += bx; v0.y += by;
                v1.x += bx; v1.y += by;
            }
            if (RESID) {
                float2 rv0 = *(const float2*)&residg[(size_t)b * sC + (size_t)row * ldC + col];
                float2 rv1 = *(const float2*)&residg[(size_t)b * sC + (size_t)(row + 8) * ldC + col];
                v0.x += rv0.x; v0.y += rv0.y;
                v1.x += rv1.x; v1.y += rv1.y;
            }
            *(float2*)&C[(size_t)row * ldC + col]       = v0;
            *(float2*)&C[(size_t)(row + 8) * ldC + col] = v1;
        }
    }
}

// ---------------- per-(b,c) mean / rstd over 4096 spatial elems -------------
__global__ void __launch_bounds__(256)
stats_kernel(const float* __restrict__ content, const float* __restrict__ style)
{
    int bc  = blockIdx.x;
    int sel = blockIdx.y;
    const float* x = (sel == 0 ? content : style) + (size_t)bc * HW;

    float s1 = 0.f, s2 = 0.f;
    for (int i = threadIdx.x * 4; i < HW; i += 256 * 4) {
        float4 v = *(const float4*)&x[i];
        s1 += v.x + v.y + v.z + v.w;
        s2 += v.x * v.x + v.y * v.y + v.z * v.z + v.w * v.w;
    }
    __shared__ float sh1[8], sh2[8];
    for (int o = 16; o > 0; o >>= 1) {
        s1 += __shfl_xor_sync(0xffffffffu, s1, o);
        s2 += __shfl_xor_sync(0xffffffffu, s2, o);
    }
    int warp = threadIdx.x >> 5, lane = threadIdx.x & 31;
    if (lane == 0) { sh1[warp] = s1; sh2[warp] = s2; }
    __syncthreads();
    if (threadIdx.x < 32) {
        s1 = (lane < 8) ? sh1[lane] : 0.f;
        s2 = (lane < 8) ? sh2[lane] : 0.f;
        for (int o = 4; o > 0; o >>= 1) {
            s1 += __shfl_xor_sync(0xffffffffu, s1, o);
            s2 += __shfl_xor_sync(0xffffffffu, s2, o);
        }
        if (lane == 0) {
            float mean = s1 / (float)HW;
            float var  = (s2 - s1 * mean) / (float)(HW - 1);
            int idx = sel * BATCH * CHN + bc;
            g_mean[idx] = mean;
            g_rstd[idx] = rsqrtf(var + EPSF);
        }
    }
}

// ------- transpose + normalize: [b][c][n] -> [b][n][c], 3 outputs ----------
__global__ void __launch_bounds__(256)
transnorm_kernel(const float* __restrict__ content, const float* __restrict__ style,
                 float* __restrict__ CNt, float* __restrict__ SNt,
                 float* __restrict__ St)
{
    __shared__ float tc[32][33], ts[32][33];
    int b  = blockIdx.z;
    int c0 = blockIdx.y * 32, n0 = blockIdx.x * 32;
    int t  = threadIdx.x;
    int r  = t >> 3, q = (t & 7) * 4;

    size_t ib = (size_t)b * CHN * HW + (size_t)(c0 + r) * HW + n0 + q;
    float mC = g_mean[b * CHN + c0 + r], rC = g_rstd[b * CHN + c0 + r];
    float4 v = *(const float4*)&content[ib];
    tc[r][q + 0] = (v.x - mC) * rC; tc[r][q + 1] = (v.y - mC) * rC;
    tc[r][q + 2] = (v.z - mC) * rC; tc[r][q + 3] = (v.w - mC) * rC;
    float4 w = *(const float4*)&style[ib];
    ts[r][q + 0] = w.x; ts[r][q + 1] = w.y; ts[r][q + 2] = w.z; ts[r][q + 3] = w.w;
    __syncthreads();

    size_t ob = (size_t)b * CHN * HW + (size_t)(n0 + r) * CHN + c0 + q;
    float4 o;
    o.x = tc[q + 0][r]; o.y = tc[q + 1][r]; o.z = tc[q + 2][r]; o.w = tc[q + 3][r];
    *(float4*)&CNt[ob] = o;

    float4 sraw;
    sraw.x = ts[q + 0][r]; sraw.y = ts[q + 1][r];
    sraw.z = ts[q + 2][r]; sraw.w = ts[q + 3][r];
    *(float4*)&St[ob] = sraw;

    int sidx = BATCH * CHN + b * CHN + c0 + q;
    float4 sm = *(const float4*)&g_mean[sidx];
    float4 sr = *(const float4*)&g_rstd[sidx];
    float4 sn;
    sn.x = (sraw.x - sm.x) * sr.x; sn.y = (sraw.y - sm.y) * sr.y;
    sn.z = (sraw.z - sm.z) * sr.z; sn.w = (sraw.w - sm.w) * sr.w;
    *(float4*)&SNt[ob] = sn;
}

// ---------------- row softmax over 4096, row cached in smem -----------------
__global__ void __launch_bounds__(256)
softmax_kernel(float* __restrict__ S)
{
    __shared__ float buf[HW];
    __shared__ float red1[8], red2[8];
    float* p = S + (size_t)blockIdx.x * HW;
    int t = threadIdx.x, lane = t & 31, warp = t >> 5;

    float m = -3.4e38f;
    for (int i = t * 4; i < HW; i += 1024) {
        float4 v = *(const float4*)&p[i];
        *(float4*)&buf[i] = v;
        m = fmaxf(m, fmaxf(fmaxf(v.x, v.y), fmaxf(v.z, v.w)));
    }
    for (int o = 16; o > 0; o >>= 1) m = fmaxf(m, __shfl_xor_sync(0xffffffffu, m, o));
    if (lane == 0) red1[warp] = m;
    __syncthreads();
    if (t < 32) {
        m = (lane < 8) ? red1[lane] : -3.4e38f;
        for (int o = 4; o > 0; o >>= 1) m = fmaxf(m, __shfl_xor_sync(0xffffffffu, m, o));
        if (lane == 0) red1[0] = m;
    }
    __syncthreads();
    m = red1[0];

    float s = 0.f;
    for (int i = t * 4; i < HW; i += 1024) {
        float4 v = *(const float4*)&buf[i];
        v.x = __expf(v.x - m); v.y = __expf(v.y - m);
        v.z = __expf(v.z - m); v.w = __expf(v.w - m);
        *(float4*)&buf[i] = v;
        s += v.x + v.y + v.z + v.w;
    }
    for (int o = 16; o > 0; o >>= 1) s += __shfl_xor_sync(0xffffffffu, s, o);
    if (lane == 0) red2[warp] = s;
    __syncthreads();
    if (t < 32) {
        s = (lane < 8) ? red2[lane] : 0.f;
        for (int o = 4; o > 0; o >>= 1) s += __shfl_xor_sync(0xffffffffu, s, o);
        if (lane == 0) red2[0] = s;
    }
    __syncthreads();
    float inv = 1.0f / red2[0];
    for (int i = t * 4; i < HW; i += 1024) {
        float4 v = *(const float4*)&buf[i];
        v.x *= inv; v.y *= inv; v.z *= inv; v.w *= inv;
        *(float4*)&p[i] = v;
    }
}

// ---------------- launch --------------------------------------------------
extern "C" void kernel_launch(void* const* d_in, const int* in_sizes, int n_in,
                              void* d_out, int out_size)
{
    const float* content = (const float*)d_in[0];
    const float* style   = (const float*)d_in[1];
    const float* Wf = (const float*)d_in[2]; const float* bf = (const float*)d_in[3];
    const float* Wg = (const float*)d_in[4]; const float* bg = (const float*)d_in[5];
    const float* Wh = (const float*)d_in[6]; const float* bh = (const float*)d_in[7];
    const float* Wo = (const float*)d_in[8]; const float* bo = (const float*)d_in[9];
    float* out = (float*)d_out;

    float *pCNt, *pSNt, *pSt, *pF, *pG, *pH, *pO, *pS;
    cudaGetSymbolAddress((void**)&pCNt, g_CNt);
    cudaGetSymbolAddress((void**)&pSNt, g_SNt);
    cudaGetSymbolAddress((void**)&pSt,  g_St);
    cudaGetSymbolAddress((void**)&pF, g_F);
    cudaGetSymbolAddress((void**)&pG, g_G);
    cudaGetSymbolAddress((void**)&pH, g_H);
    cudaGetSymbolAddress((void**)&pO, g_O);
    cudaGetSymbolAddress((void**)&pS, g_S);

    cudaFuncSetAttribute(bf16_gemm_kernel<0, false>,
                         cudaFuncAttributeMaxDynamicSharedMemorySize, BGK_SMEMB);
    cudaFuncSetAttribute(bf16_gemm_kernel<1, false>,
                         cudaFuncAttributeMaxDynamicSharedMemorySize, BGK_SMEMB);
    cudaFuncSetAttribute(bf16_gemm_kernel<2, false>,
                         cudaFuncAttributeMaxDynamicSharedMemorySize, BGK_SMEMB);
    cudaFuncSetAttribute(bf16_gemm_kernel<1, true>,
                         cudaFuncAttributeMaxDynamicSharedMemorySize, BGK_SMEMB);

    const size_t sBCHW = (size_t)CHN * HW;
    const size_t sBHH  = (size_t)HW * HW;

    // 1) normalization stats
    stats_kernel<<<dim3(BATCH * CHN, 2), 256>>>(content, style);

    // 2) transpose + normalize: CN_t, SN_t, St  ([b][n][c])
    transnorm_kernel<<<dim3(HW / 32, CHN / 32, BATCH), 256>>>(
        content, style, pCNt, pSNt, pSt);

    // 3) F_t[n,c] = CN_t[n,:] . Wf[c,:]   (bias per col)
    bf16_gemm_kernel<2, false><<<dim3(CHN / 128, HW / 128, BATCH), 512, BGK_SMEMB>>>(
        pCNt, Wf, bf, nullptr, pF, CHN, CHN, CHN, CHN, sBCHW, 0, sBCHW);

    // 4) G_t[n,c] = SN_t[n,:] . Wg[c,:]   (bias per col)
    bf16_gemm_kernel<2, false><<<dim3(CHN / 128, HW / 128, BATCH), 512, BGK_SMEMB>>>(
        pSNt, Wg, bg, nullptr, pG, CHN, CHN, CHN, CHN, sBCHW, 0, sBCHW);

    // 5) H[c,m] = Wh[c,:] . St[m,:]       (bias per row)
    bf16_gemm_kernel<1, false><<<dim3(HW / 128, CHN / 128, BATCH), 512, BGK_SMEMB>>>(
        Wh, pSt, bh, nullptr, pH, CHN, CHN, CHN, HW, 0, sBCHW, sBCHW);

    // 6) S[n,m] = F_t[n,:] . G_t[m,:]
    bf16_gemm_kernel<0, false><<<dim3(HW / 128, HW / 128, BATCH), 512, BGK_SMEMB>>>(
        pF, pG, nullptr, nullptr, pS, CHN, CHN, CHN, HW,
        sBCHW, sBCHW, sBHH);

    // 7) softmax rows of S
    softmax_kernel<<<BATCH * HW, 256>>>(pS);

    // 8) O_t[n,c] = P[n,:] . H[c,:]       (K = HW)
    bf16_gemm_kernel<0, false><<<dim3(CHN / 128, HW / 128, BATCH), 512, BGK_SMEMB>>>(
        pS, pH, nullptr, nullptr, pO, HW, HW, HW, CHN,
        sBHH, sBCHW, sBCHW);

    // 9) out[c,n] = Wo[c,:] . O_t[n,:] + bo + content   (bias per row + resid)
    bf16_gemm_kernel<1, true><<<dim3(HW / 128, CHN / 128, BATCH), 512, BGK_SMEMB>>>(
        Wo, pO, bo, content, out, CHN, CHN, CHN, HW, 0, sBCHW, sBCHW);
}